// round 7
// baseline (speedup 1.0000x reference)
#include <cuda_runtime.h>

// out[t,b,i,e] = x[t,b,i] * W[i,e] + b[e]
// T=8, B=64, D=512, E=256. k = t*B+b in [0,512).
// out4[(k*512 + i)*64 + e4] = x[k*512 + i] * W4[i*64 + e4] + b4[e4]
//
// Grid: x = i (512), y = k-chunk (8). Block: 256 thr = 4 kg x 64 e4.
// W/b register-cached; 16 batched x loads; 16 FMA4 + STG.128.
// R6: __stwt write-through stores to keep DRAM continuously busy
// (R5 ncu showed DRAM idle 34% of cycles — lazy L2 writeback).

#define D_DIM 512
#define E4    64
#define K_CHUNKS 8
#define K_PER_CHUNK 64
#define KK 16

__global__ __launch_bounds__(256) void dense_embed_kernel(
    const float* __restrict__ x,    // [512 * 512]
    const float4* __restrict__ W4,  // [512 * 64]
    const float4* __restrict__ b4,  // [64]
    float4* __restrict__ out4)      // [512 * 512 * 64]
{
    const unsigned i  = blockIdx.x;               // 0..511
    const unsigned e4 = threadIdx.x & (E4 - 1);   // 0..63
    const unsigned kg = threadIdx.x >> 6;         // 0..3
    const unsigned k0 = blockIdx.y * K_PER_CHUNK + kg * KK;

    // Per-thread invariants
    const float4 w  = __ldg(&W4[i * E4 + e4]);
    const float4 bb = __ldg(&b4[e4]);

    const float* xp = x + (size_t)k0 * D_DIM + i;
    float4* op = out4 + ((size_t)k0 * D_DIM + i) * E4 + e4;

    // Batch all 16 x loads up front — independent, fully overlapped.
    float xv[KK];
    #pragma unroll
    for (int kk = 0; kk < KK; kk++)
        xv[kk] = __ldg(&xp[(size_t)kk * D_DIM]);

    // Pure store stream: 16 back-to-back FMA4 + write-through STG.128.
    #pragma unroll
    for (int kk = 0; kk < KK; kk++) {
        float4 o;
        o.x = fmaf(xv[kk], w.x, bb.x);
        o.y = fmaf(xv[kk], w.y, bb.y);
        o.z = fmaf(xv[kk], w.z, bb.z);
        o.w = fmaf(xv[kk], w.w, bb.w);
        __stwt(&op[(size_t)kk * D_DIM * E4], o);   // write-through -> DRAM stays busy
    }
}

extern "C" void kernel_launch(void* const* d_in, const int* in_sizes, int n_in,
                              void* d_out, int out_size) {
    const float*  x  = (const float*)d_in[0];
    const float4* W4 = (const float4*)d_in[1];
    const float4* b4 = (const float4*)d_in[2];
    float4* out4 = (float4*)d_out;

    dim3 grid(D_DIM, K_CHUNKS);   // 4096 blocks
    dense_embed_kernel<<<grid, 256>>>(x, W4, b4, out4);
}

// round 8
// speedup vs baseline: 1.0115x; 1.0115x over previous
#include <cuda_runtime.h>

// out[t,b,i,e] = x[t,b,i] * W[i,e] + b[e]
// T=8, B=64, D=512, E=256. k = t*B+b in [0,512).
// out4[(k*512 + i)*64 + e4] = x[k*512 + i] * W4[i*64 + e4] + b4[e4]
//
// Grid: x = i (512), y = k-chunk (8). Block: 256 thr = 4 kg x 64 e4.
// W/b register-cached; 16 batched x loads; 16 FMA4 + STG.128.
// R7: plain write-back stores (single-variable test vs __stcs/__stwt).
// Evidence so far: stcs 40.4-40.5us, stwt 41.2us; effective write rate
// already 6.63 TB/s (~83% of spec) -> chasing the last few percent.

#define D_DIM 512
#define E4    64
#define K_CHUNKS 8
#define K_PER_CHUNK 64
#define KK 16

__global__ __launch_bounds__(256) void dense_embed_kernel(
    const float* __restrict__ x,    // [512 * 512]
    const float4* __restrict__ W4,  // [512 * 64]
    const float4* __restrict__ b4,  // [64]
    float4* __restrict__ out4)      // [512 * 512 * 64]
{
    const unsigned i  = blockIdx.x;               // 0..511
    const unsigned e4 = threadIdx.x & (E4 - 1);   // 0..63
    const unsigned kg = threadIdx.x >> 6;         // 0..3
    const unsigned k0 = blockIdx.y * K_PER_CHUNK + kg * KK;

    // Per-thread invariants
    const float4 w  = __ldg(&W4[i * E4 + e4]);
    const float4 bb = __ldg(&b4[e4]);

    const float* xp = x + (size_t)k0 * D_DIM + i;
    float4* op = out4 + ((size_t)k0 * D_DIM + i) * E4 + e4;

    // Batch all 16 x loads up front — independent, fully overlapped.
    float xv[KK];
    #pragma unroll
    for (int kk = 0; kk < KK; kk++)
        xv[kk] = __ldg(&xp[(size_t)kk * D_DIM]);

    // Pure store stream: 16 back-to-back FMA4 + default STG.128 (.wb policy).
    #pragma unroll
    for (int kk = 0; kk < KK; kk++) {
        float4 o;
        o.x = fmaf(xv[kk], w.x, bb.x);
        o.y = fmaf(xv[kk], w.y, bb.y);
        o.z = fmaf(xv[kk], w.z, bb.z);
        o.w = fmaf(xv[kk], w.w, bb.w);
        op[(size_t)kk * D_DIM * E4] = o;
    }
}

extern "C" void kernel_launch(void* const* d_in, const int* in_sizes, int n_in,
                              void* d_out, int out_size) {
    const float*  x  = (const float*)d_in[0];
    const float4* W4 = (const float4*)d_in[1];
    const float4* b4 = (const float4*)d_in[2];
    float4* out4 = (float4*)d_out;

    dim3 grid(D_DIM, K_CHUNKS);   // 4096 blocks
    dense_embed_kernel<<<grid, 256>>>(x, W4, b4, out4);
}

// round 9
// speedup vs baseline: 1.0798x; 1.0675x over previous
#include <cuda_runtime.h>

// out[t,b,i,e] = x[t,b,i] * W[i,e] + b[e]
// T=8, B=64, D=512, E=256. k = t*B+b in [0,512).
// out4[(k*512 + i)*64 + e4] = x[k*512 + i] * W4[i*64 + e4] + b4[e4]
//
// Best-known config (R5): W/b register-cached, 16 batched x loads,
// 16 FMA4 + __stcs STG.128 (policy sweep: stcs 40.4 < wt 41.2 < wb 41.4 ncu).
// R8 experiment: grid dims swapped (x=chunk, y=i) so concurrently-resident
// blocks spread writes across all 8 chunks (8x wider instantaneous address
// window -> more DRAM bank-rows open, fewer row conflicts in write drain).

#define D_DIM 512
#define E4    64
#define K_CHUNKS 8
#define K_PER_CHUNK 64
#define KK 16

__global__ __launch_bounds__(256) void dense_embed_kernel(
    const float* __restrict__ x,    // [512 * 512]
    const float4* __restrict__ W4,  // [512 * 64]
    const float4* __restrict__ b4,  // [64]
    float4* __restrict__ out4)      // [512 * 512 * 64]
{
    const unsigned i  = blockIdx.y;               // 0..511
    const unsigned e4 = threadIdx.x & (E4 - 1);   // 0..63
    const unsigned kg = threadIdx.x >> 6;         // 0..3
    const unsigned k0 = blockIdx.x * K_PER_CHUNK + kg * KK;

    // Per-thread invariants
    const float4 w  = __ldg(&W4[i * E4 + e4]);
    const float4 bb = __ldg(&b4[e4]);

    const float* xp = x + (size_t)k0 * D_DIM + i;
    float4* op = out4 + ((size_t)k0 * D_DIM + i) * E4 + e4;

    // Batch all 16 x loads up front — independent, fully overlapped.
    float xv[KK];
    #pragma unroll
    for (int kk = 0; kk < KK; kk++)
        xv[kk] = __ldg(&xp[(size_t)kk * D_DIM]);

    // Pure store stream: 16 back-to-back FMA4 + evict-first STG.128.
    #pragma unroll
    for (int kk = 0; kk < KK; kk++) {
        float4 o;
        o.x = fmaf(xv[kk], w.x, bb.x);
        o.y = fmaf(xv[kk], w.y, bb.y);
        o.z = fmaf(xv[kk], w.z, bb.z);
        o.w = fmaf(xv[kk], w.w, bb.w);
        __stcs(&op[(size_t)kk * D_DIM * E4], o);
    }
}

extern "C" void kernel_launch(void* const* d_in, const int* in_sizes, int n_in,
                              void* d_out, int out_size) {
    const float*  x  = (const float*)d_in[0];
    const float4* W4 = (const float4*)d_in[1];
    const float4* b4 = (const float4*)d_in[2];
    float4* out4 = (float4*)d_out;

    dim3 grid(K_CHUNKS, D_DIM);   // 8 x 512 = 4096 blocks, chunk-fastest order
    dense_embed_kernel<<<grid, 256>>>(x, W4, b4, out4);
}